// round 2
// baseline (speedup 1.0000x reference)
#include <cuda_runtime.h>
#include <cuda_bf16.h>

#define NF 13776
#define NV 6890
#define KC 8

// ---------------- scratch (static device globals; no allocs) ----------------
__device__ float g_tri [NF * 9];   // [face][vert0 xyz, vert1 xyz, vert2 xyz]
__device__ float g_bmin[3][NF];    // SoA AABB min per axis
__device__ float g_bmax[3][NF];    // SoA AABB max per axis
__device__ int   g_face[3][NF];    // SoA face vertex indices
__device__ int   g_pairs[NF * KC]; // intruder index or -1

// ---------------- kernel 1: gather + AABB + zero output ----------------
__global__ void setup_kernel(const float* __restrict__ verts,
                             const int*   __restrict__ faces,
                             float* __restrict__ out) {
    int t = blockIdx.x * blockDim.x + threadIdx.x;
    if (t == 0) out[0] = 0.0f;
    if (t >= NF) return;

    int i0 = faces[3 * t + 0];
    int i1 = faces[3 * t + 1];
    int i2 = faces[3 * t + 2];

    float v0x = verts[3 * i0 + 0], v0y = verts[3 * i0 + 1], v0z = verts[3 * i0 + 2];
    float v1x = verts[3 * i1 + 0], v1y = verts[3 * i1 + 1], v1z = verts[3 * i1 + 2];
    float v2x = verts[3 * i2 + 0], v2y = verts[3 * i2 + 1], v2z = verts[3 * i2 + 2];

    float* tr = &g_tri[t * 9];
    tr[0] = v0x; tr[1] = v0y; tr[2] = v0z;
    tr[3] = v1x; tr[4] = v1y; tr[5] = v1z;
    tr[6] = v2x; tr[7] = v2y; tr[8] = v2z;

    g_bmin[0][t] = fminf(v0x, fminf(v1x, v2x));
    g_bmin[1][t] = fminf(v0y, fminf(v1y, v2y));
    g_bmin[2][t] = fminf(v0z, fminf(v1z, v2z));
    g_bmax[0][t] = fmaxf(v0x, fmaxf(v1x, v2x));
    g_bmax[1][t] = fmaxf(v0y, fmaxf(v1y, v2y));
    g_bmax[2][t] = fmaxf(v0z, fmaxf(v1z, v2z));

    g_face[0][t] = i0;
    g_face[1][t] = i1;
    g_face[2][t] = i2;
}

// ---------------- kernel 2: broad phase, warp per receiver ----------------
// Reproduces jax.lax.top_k on 0/1 validity: the first KC valid j in ascending
// order (top_k is stable: ties -> lowest index first).
__global__ void broad_kernel() {
    int gtid = blockIdx.x * blockDim.x + threadIdx.x;
    int i    = gtid >> 5;      // warp id = receiver face
    int lane = gtid & 31;
    if (i >= NF) return;

    float ilx = g_bmin[0][i], ily = g_bmin[1][i], ilz = g_bmin[2][i];
    float ihx = g_bmax[0][i], ihy = g_bmax[1][i], ihz = g_bmax[2][i];
    int fi0 = g_face[0][i], fi1 = g_face[1][i], fi2 = g_face[2][i];

    int cnt = 0;
    for (int base = 0; base < NF && cnt < KC; base += 32) {
        int j = base + lane;
        bool ok = false;
        if (j < NF) {
            float jlx = g_bmin[0][j], jly = g_bmin[1][j], jlz = g_bmin[2][j];
            float jhx = g_bmax[0][j], jhy = g_bmax[1][j], jhz = g_bmax[2][j];
            ok = (ilx <= jhx) & (jlx <= ihx) &
                 (ily <= jhy) & (jly <= ihy) &
                 (ilz <= jhz) & (jlz <= ihz);
            if (ok) {
                int fj0 = g_face[0][j], fj1 = g_face[1][j], fj2 = g_face[2][j];
                bool share = (fi0 == fj0) | (fi0 == fj1) | (fi0 == fj2) |
                             (fi1 == fj0) | (fi1 == fj1) | (fi1 == fj2) |
                             (fi2 == fj0) | (fi2 == fj1) | (fi2 == fj2);
                ok = !share;
            }
        }
        unsigned m = __ballot_sync(0xffffffffu, ok);
        int rank = __popc(m & ((1u << lane) - 1u));
        if (ok && (cnt + rank) < KC)
            g_pairs[i * KC + cnt + rank] = j;
        cnt = min(KC, cnt + __popc(m));
    }
    // pad the tail with -1 (cnt is warp-uniform here)
    if (lane < KC && lane >= cnt)
        g_pairs[i * KC + lane] = -1;
}

// ---------------- cone-field penalty (matches jnp fp32 math) ----------------
// SIGMA = 0.5 -> r/SIGMA = 2r, h/SIGMA = 2h. POINT2PLANE=False, PENALIZE_OUTSIDE=True.
__device__ __forceinline__ float cone_pen(const float* __restrict__ s,
                                          const float* __restrict__ p) {
    float e0x = s[3] - s[0], e0y = s[4] - s[1], e0z = s[5] - s[2];
    float e1x = s[6] - s[0], e1y = s[7] - s[1], e1z = s[8] - s[2];
    float nx = e0y * e1z - e0z * e1y;
    float ny = e0z * e1x - e0x * e1z;
    float nz = e0x * e1y - e0y * e1x;
    float inv = 1.0f / (sqrtf(nx * nx + ny * ny + nz * nz) + 1e-8f);
    nx *= inv; ny *= inv; nz *= inv;
    float cx = (s[0] + s[3] + s[6]) * (1.0f / 3.0f);
    float cy = (s[1] + s[4] + s[7]) * (1.0f / 3.0f);
    float cz = (s[2] + s[5] + s[8]) * (1.0f / 3.0f);

    float acc = 0.0f;
#pragma unroll
    for (int v = 0; v < 3; ++v) {
        float ux = p[3 * v + 0] - cx;
        float uy = p[3 * v + 1] - cy;
        float uz = p[3 * v + 2] - cz;
        float h = ux * nx + uy * ny + uz * nz;
        float wx = ux - h * nx, wy = uy - h * ny, wz = uz - h * nz;
        float r = sqrtf(wx * wx + wy * wy + wz * wz);
        float radial = fmaxf(1.0f - 2.0f * r, 0.0f);
        float depth  = fmaxf(-h, 0.0f) + fmaxf(h, 0.0f) * expf(-2.0f * h);
        float phi = radial * depth;
        acc += phi * phi;
    }
    return acc;
}

// ---------------- kernel 3: narrow phase + reduction ----------------
__global__ void narrow_kernel(float* __restrict__ out) {
    int t = blockIdx.x * blockDim.x + threadIdx.x;
    float acc = 0.0f;
    if (t < NF * KC) {
        int j = g_pairs[t];
        if (j >= 0) {
            int i = t >> 3;
            const float* a = &g_tri[i * 9];
            const float* b = &g_tri[j * 9];
            float ar[9], br[9];
#pragma unroll
            for (int q = 0; q < 9; ++q) { ar[q] = a[q]; br[q] = b[q]; }
            acc = cone_pen(ar, br) + cone_pen(br, ar);
        }
    }
    // warp reduce
#pragma unroll
    for (int off = 16; off > 0; off >>= 1)
        acc += __shfl_down_sync(0xffffffffu, acc, off);

    __shared__ float ssum[8];
    int lane = threadIdx.x & 31;
    int wid  = threadIdx.x >> 5;
    if (lane == 0) ssum[wid] = acc;
    __syncthreads();
    if (wid == 0) {
        float v = (lane < (blockDim.x >> 5)) ? ssum[lane] : 0.0f;
#pragma unroll
        for (int off = 4; off > 0; off >>= 1)
            v += __shfl_down_sync(0xffffffffu, v, off);
        if (lane == 0 && v != 0.0f) atomicAdd(out, v);
    }
}

// ---------------- launch ----------------
extern "C" void kernel_launch(void* const* d_in, const int* in_sizes, int n_in,
                              void* d_out, int out_size) {
    const float* verts = (const float*)d_in[0];
    const int*   faces = (const int*)d_in[1];
    float* out = (float*)d_out;

    setup_kernel<<<(NF + 255) / 256, 256>>>(verts, faces, out);

    int warps = NF;                      // one warp per receiver face
    int threads = warps * 32;
    broad_kernel<<<(threads + 255) / 256, 256>>>();

    int npair = NF * KC;
    narrow_kernel<<<(npair + 255) / 256, 256>>>(out);
}